// round 1
// baseline (speedup 1.0000x reference)
#include <cuda_runtime.h>
#include <math.h>

// Problem constants
#define NN 32
#define CC 128
#define SS 4096
#define KK 64

// Kernel-1 tiling
#define TILE 64          // pixels per tile
#define PIX 256          // pixels per block
#define CHUNKS 16        // SS / PIX
#define THREADS 256

#define WPAD 68          // padded row length for wsT [C][K]
#define XPAD 68          // padded row length for xsT [C][TILE]
#define APAD 68          // padded row length for as  [TILE][K]

// shared layout (floats)
#define OFF_WST 0
#define OFF_XST (OFF_WST + CC * WPAD)          // 8704
#define OFF_AS  (OFF_XST + CC * XPAD)          // 17408
#define OFF_RI  (OFF_AS  + TILE * APAD)        // 21760
#define OFF_RA  (OFF_RI  + 64)                 // 21824
#define OFF_RB  (OFF_RA  + 256)                // 22080
#define SMEM_FLOATS (OFF_RB + 256)             // 22336
#define SMEM_BYTES (SMEM_FLOATS * 4)           // 89344

// Scratch (device globals; no allocation allowed)
__device__ float g_vlad_part[NN * CHUNKS * KK * CC];  // 16 MB
__device__ float g_asum_part[NN * CHUNKS * KK];
__device__ float g_outpart[NN * 16 * CC];

// ---------------------------------------------------------------------------
// Kernel 1: per (n, chunk) block — normalize, logits, softmax, vlad partials
// ---------------------------------------------------------------------------
__global__ void __launch_bounds__(THREADS, 2)
netvlad_k1(const float* __restrict__ x,
           const float* __restrict__ conv_w,
           const float* __restrict__ conv_b)
{
    extern __shared__ float sm[];
    float* wsT  = sm + OFF_WST;   // [C][WPAD] : wsT[c][k]
    float* xsT  = sm + OFF_XST;   // [C][XPAD] : xsT[c][p]
    float* as_  = sm + OFF_AS;    // [TILE][APAD] : as[p][k]
    float* rinv = sm + OFF_RI;    // [64]
    float* redA = sm + OFF_RA;    // [256]
    float* redB = sm + OFF_RB;    // [256]

    const int tid   = threadIdx.x;
    const int chunk = blockIdx.x;
    const int n     = blockIdx.y;

    // --- load conv_w transposed into shared ---
    for (int idx = tid; idx < KK * CC; idx += THREADS) {
        int c = idx & 127, k = idx >> 7;
        wsT[c * WPAD + k] = conv_w[idx];     // conv_w[k][c], idx = k*128+c
    }

    // logits mapping: 4k x 4p per thread
    const int lk0 = (tid >> 4) * 4;
    const int lp0 = (tid & 15) * 4;
    float bia[4];
#pragma unroll
    for (int i = 0; i < 4; i++) bia[i] = conv_b[lk0 + i];

    // accumulate mapping: 4k x 8c per thread (c strided by 16)
    const int ak0 = (tid >> 4) * 4;
    const int acg = (tid & 15);

    float vacc[4][8];
#pragma unroll
    for (int i = 0; i < 4; i++)
#pragma unroll
        for (int j = 0; j < 8; j++) vacc[i][j] = 0.f;
    float sacc[4] = {0.f, 0.f, 0.f, 0.f};

    const float* xn = x + (size_t)n * CC * SS + chunk * PIX;

    for (int tile = 0; tile < PIX / TILE; ++tile) {
        const int sbase = tile * TILE;
        __syncthreads();   // previous accumulate done before overwriting xsT

        // --- load tile [C][TILE] coalesced ---
        for (int idx = tid; idx < CC * TILE; idx += THREADS) {
            int c = idx >> 6, p = idx & 63;
            xsT[c * XPAD + p] = xn[c * SS + sbase + p];
        }
        __syncthreads();

        // --- per-pixel L2 norm over C ---
        {
            int p = tid & 63, q = tid >> 6;
            float ss = 0.f;
#pragma unroll
            for (int cc = 0; cc < 32; cc++) {
                float v = xsT[(q * 32 + cc) * XPAD + p];
                ss += v * v;
            }
            redA[q * 64 + p] = ss;
            __syncthreads();
            if (tid < 64) {
                float tot = redA[tid] + redA[64 + tid] + redA[128 + tid] + redA[192 + tid];
                rinv[tid] = 1.0f / fmaxf(sqrtf(tot), 1e-12f);
            }
            __syncthreads();
            for (int idx = tid; idx < CC * TILE; idx += THREADS) {
                int c = idx >> 6, pp = idx & 63;
                xsT[c * XPAD + pp] *= rinv[pp];
            }
            __syncthreads();
        }

        // --- logits: 64k x 64p register-tiled matmul ---
        {
            float lac[4][4];
#pragma unroll
            for (int i = 0; i < 4; i++)
#pragma unroll
                for (int j = 0; j < 4; j++) lac[i][j] = bia[i];

            const float* wp = wsT + lk0;
            const float* xp = xsT + lp0;
#pragma unroll 4
            for (int c = 0; c < CC; ++c) {
                float4 w4 = *(const float4*)wp;  wp += WPAD;
                float4 x4 = *(const float4*)xp;  xp += XPAD;
                float wv[4] = {w4.x, w4.y, w4.z, w4.w};
                float xv[4] = {x4.x, x4.y, x4.z, x4.w};
#pragma unroll
                for (int i = 0; i < 4; i++)
#pragma unroll
                    for (int j = 0; j < 4; j++)
                        lac[i][j] += wv[i] * xv[j];
            }
#pragma unroll
            for (int j = 0; j < 4; j++) {
                float4 o = make_float4(lac[0][j], lac[1][j], lac[2][j], lac[3][j]);
                *(float4*)&as_[(lp0 + j) * APAD + lk0] = o;
            }
        }
        __syncthreads();

        // --- softmax over k per pixel (4 threads / pixel) ---
        {
            int p = tid >> 2, g = tid & 3;
            float m = -1e30f;
#pragma unroll
            for (int i = 0; i < 16; i++)
                m = fmaxf(m, as_[p * APAD + g * 16 + i]);
            redA[p * 4 + g] = m;
            __syncthreads();
            float mm = fmaxf(fmaxf(redA[p * 4 + 0], redA[p * 4 + 1]),
                             fmaxf(redA[p * 4 + 2], redA[p * 4 + 3]));
            float s = 0.f;
#pragma unroll
            for (int i = 0; i < 16; i++) {
                float e = __expf(as_[p * APAD + g * 16 + i] - mm);
                as_[p * APAD + g * 16 + i] = e;
                s += e;
            }
            redB[p * 4 + g] = s;
            __syncthreads();
            float tot = redB[p * 4 + 0] + redB[p * 4 + 1] + redB[p * 4 + 2] + redB[p * 4 + 3];
            float r = 1.0f / tot;
#pragma unroll
            for (int i = 0; i < 16; i++)
                as_[p * APAD + g * 16 + i] *= r;
        }
        __syncthreads();

        // --- VLAD accumulate: vlad[k][c] += a[p][k] * xhat[c][p] ---
        {
#pragma unroll 2
            for (int p = 0; p < TILE; p += 2) {
                float4 a0 = *(const float4*)&as_[p * APAD + ak0];
                float4 a1 = *(const float4*)&as_[(p + 1) * APAD + ak0];
                float a0v[4] = {a0.x, a0.y, a0.z, a0.w};
                float a1v[4] = {a1.x, a1.y, a1.z, a1.w};
                float2 xv[8];
#pragma unroll
                for (int j = 0; j < 8; j++)
                    xv[j] = *(const float2*)&xsT[(acg + 16 * j) * XPAD + p];
#pragma unroll
                for (int i = 0; i < 4; i++)
#pragma unroll
                    for (int j = 0; j < 8; j++)
                        vacc[i][j] += a0v[i] * xv[j].x + a1v[i] * xv[j].y;
                if (acg == 0) {
#pragma unroll
                    for (int i = 0; i < 4; i++) sacc[i] += a0v[i] + a1v[i];
                }
            }
        }
    }

    // --- write partials ---
    {
        float* vp = g_vlad_part + (size_t)(n * CHUNKS + chunk) * KK * CC;
#pragma unroll
        for (int i = 0; i < 4; i++)
#pragma unroll
            for (int j = 0; j < 8; j++)
                vp[(ak0 + i) * CC + acg + 16 * j] = vacc[i][j];
        if (acg == 0) {
#pragma unroll
            for (int i = 0; i < 4; i++)
                g_asum_part[(n * CHUNKS + chunk) * KK + ak0 + i] = sacc[i];
        }
    }
}

// ---------------------------------------------------------------------------
// Kernel 2: reduce chunk partials, subtract centroid term, intra-normalize,
//           apply fc weight; one block per (n, group-of-4-k)
// ---------------------------------------------------------------------------
__global__ void netvlad_k2(const float* __restrict__ centroids,
                           const float* __restrict__ fc_w)
{
    const int kg = blockIdx.x;      // 0..15
    const int n  = blockIdx.y;      // 0..31
    const int c  = threadIdx.x;     // 0..127
    __shared__ float sred[4];

    float acc = 0.f;
    for (int kk = 0; kk < 4; kk++) {
        const int k = kg * 4 + kk;
        float asum = 0.f;
#pragma unroll
        for (int ch = 0; ch < CHUNKS; ch++)
            asum += g_asum_part[(n * CHUNKS + ch) * KK + k];

        float v = -asum * centroids[k * CC + c];
#pragma unroll
        for (int ch = 0; ch < CHUNKS; ch++)
            v += g_vlad_part[((size_t)(n * CHUNKS + ch) * KK + k) * CC + c];

        // block reduce v*v over 128 threads
        float ss = v * v;
#pragma unroll
        for (int off = 16; off > 0; off >>= 1)
            ss += __shfl_xor_sync(0xffffffffu, ss, off);
        if ((c & 31) == 0) sred[c >> 5] = ss;
        __syncthreads();
        float tot = sred[0] + sred[1] + sred[2] + sred[3];
        __syncthreads();

        float inv = 1.0f / fmaxf(sqrtf(tot), 1e-12f);
        acc += v * inv * fc_w[k];
    }
    g_outpart[(n * 16 + kg) * CC + c] = acc;
}

// ---------------------------------------------------------------------------
// Kernel 3: final deterministic reduction over the 16 k-groups
// ---------------------------------------------------------------------------
__global__ void netvlad_k3(float* __restrict__ out)
{
    const int n = blockIdx.x;
    const int c = threadIdx.x;
    float s = 0.f;
#pragma unroll
    for (int kg = 0; kg < 16; kg++)
        s += g_outpart[(n * 16 + kg) * CC + c];
    out[n * CC + c] = s;
}

// ---------------------------------------------------------------------------
extern "C" void kernel_launch(void* const* d_in, const int* in_sizes, int n_in,
                              void* d_out, int out_size)
{
    const float* x      = (const float*)d_in[0];  // [32,128,64,64]
    const float* conv_w = (const float*)d_in[1];  // [64,128]
    const float* conv_b = (const float*)d_in[2];  // [64]
    const float* cent   = (const float*)d_in[3];  // [64,128]
    const float* fc_w   = (const float*)d_in[4];  // [1,64]
    float* out = (float*)d_out;                   // [32,128]

    cudaFuncSetAttribute(netvlad_k1,
                         cudaFuncAttributeMaxDynamicSharedMemorySize,
                         SMEM_BYTES);

    dim3 g1(CHUNKS, NN);
    netvlad_k1<<<g1, THREADS, SMEM_BYTES>>>(x, conv_w, conv_b);

    dim3 g2(16, NN);
    netvlad_k2<<<g2, CC>>>(cent, fc_w);

    netvlad_k3<<<NN, CC>>>(out);
}

// round 4
// speedup vs baseline: 3.3169x; 3.3169x over previous
#include <cuda_runtime.h>
#include <cstdint>
#include <math.h>

#define NN 32
#define CC 128
#define SSZ 4096
#define KK 64
#define NCHUNK 4
#define CHUNK_P 1024
#define SUBT 128
#define NSUB 8
#define THREADS 256

// padded row lengths in floats (136 = 8 banks mod 32 -> conflict-free frags)
#define XPADF 136
#define WPADF 136
#define APADF 136

// smem byte offsets
#define OFF_XS   0                      // xs [128 p][136] : 69632 B
#define OFF_WS   69632                  // wk [64 k][136]  : 34816 B
#define OFF_AS   104448                 // as [64 k][136]  : 34816 B
#define OFF_RED  139264                 // 256 floats
#define OFF_RINV 140288                 // 128 floats
#define OFF_ASR  140800                 // 512 floats
#define SMEM_BYTES 142848

// scratch (no allocation allowed)
__device__ float g_vlad_part[NN * NCHUNK * KK * CC];   // [n][ch][k][c]
__device__ float g_asum_part[NN * NCHUNK * KK];
__device__ float g_outpart[NN * 16 * CC];

// ---------------------------------------------------------------------------
__device__ __forceinline__ float tf32r(float x) {
    float r;
    asm("cvt.rna.tf32.f32 %0, %1;" : "=f"(r) : "f"(x));
    return r;
}
__device__ __forceinline__ void mma_tf32(float* d, uint32_t a0, uint32_t a1,
                                         uint32_t a2, uint32_t a3,
                                         uint32_t b0, uint32_t b1) {
    asm volatile(
        "mma.sync.aligned.m16n8k8.row.col.f32.tf32.tf32.f32 "
        "{%0,%1,%2,%3}, {%4,%5,%6,%7}, {%8,%9}, {%0,%1,%2,%3};"
        : "+f"(d[0]), "+f"(d[1]), "+f"(d[2]), "+f"(d[3])
        : "r"(a0), "r"(a1), "r"(a2), "r"(a3), "r"(b0), "r"(b1));
}

// column permutation within 8-blocks: pairs (j, j+4) adjacent
__device__ __forceinline__ int perm8(int j) { return 2 * (j & 3) + ((j >> 2) & 1); }

// ---------------------------------------------------------------------------
// Kernel 1: per (n, chunk of 1024 px).  tf32 mma.sync for both GEMMs.
// ---------------------------------------------------------------------------
__global__ void __launch_bounds__(THREADS, 1)
netvlad_k1(const float* __restrict__ x,
           const float* __restrict__ conv_w,
           const float* __restrict__ conv_b)
{
    extern __shared__ char smem[];
    float* red  = (float*)(smem + OFF_RED);
    float* rinv = (float*)(smem + OFF_RINV);
    float* asr  = (float*)(smem + OFF_ASR);

    const int tid  = threadIdx.x;
    const int wid  = tid >> 5, lane = tid & 31;
    const int g    = lane >> 2, tg = lane & 3;
    const int ch   = blockIdx.x, n = blockIdx.y;
    const int p    = tid & 127;          // pixel within subtile
    const int c0h  = (tid >> 7) * 64;    // channel half
    const int p0   = wid * 16;           // GEMM1 p-strip
    const int mw   = wid & 3, nh = wid >> 2;   // GEMM2 region
    const int pg   = perm8(g);

    // W -> wk[k][perm(c)] tf32
    for (int idx = tid; idx < KK * CC; idx += THREADS) {
        int k = idx >> 7, c = idx & 127;
        int pos = (c & ~7) + perm8(c);
        *(float*)(smem + OFF_WS + (k * WPADF + pos) * 4) = tf32r(conv_w[idx]);
    }
    float bias[16];
#pragma unroll
    for (int i = 0; i < 16; i++)
        bias[i] = conv_b[(i >> 1) * 8 + tg * 2 + (i & 1)];

    float vacc[8][4];
#pragma unroll
    for (int i = 0; i < 8; i++)
#pragma unroll
        for (int j = 0; j < 4; j++) vacc[i][j] = 0.f;
    float ap[16];
#pragma unroll
    for (int i = 0; i < 16; i++) ap[i] = 0.f;

#pragma unroll 1
    for (int st = 0; st < NSUB; ++st) {
        const int s0 = ch * CHUNK_P + st * SUBT;
        __syncthreads();   // previous subtile's GEMM2 done reading xs/as

        // ---- load x -> regs, fused sumsq (coalesced over p) ----
        float xv[64];
        float ssum = 0.f;
        const float* xp = x + ((size_t)(n * CC + c0h)) * SSZ + s0 + p;
#pragma unroll
        for (int i = 0; i < 64; i++) {
            float v = xp[(size_t)i * SSZ];
            xv[i] = v;
            ssum += v * v;
        }
        red[tid] = ssum;
        __syncthreads();
        if (tid < 128)
            rinv[tid] = 1.0f / fmaxf(sqrtf(red[tid] + red[tid + 128]), 1e-12f);
        __syncthreads();

        // ---- normalize, tf32-round, store xs[p][perm(c)] ----
        {
            const float rv = rinv[p];
            char* rowp = smem + OFF_XS + (p * XPADF + c0h) * 4;
#pragma unroll
            for (int b = 0; b < 8; b++) {
                float4 s1 = make_float4(tf32r(xv[8*b+0]*rv), tf32r(xv[8*b+4]*rv),
                                        tf32r(xv[8*b+1]*rv), tf32r(xv[8*b+5]*rv));
                float4 s2 = make_float4(tf32r(xv[8*b+2]*rv), tf32r(xv[8*b+6]*rv),
                                        tf32r(xv[8*b+3]*rv), tf32r(xv[8*b+7]*rv));
                *(float4*)(rowp + b * 32)      = s1;
                *(float4*)(rowp + b * 32 + 16) = s2;
            }
        }
        __syncthreads();

        // ---- GEMM1: logits[p0..p0+15][0..63] = x̂ · Wᵀ ----
        float lac[8][4];
#pragma unroll
        for (int i = 0; i < 8; i++)
#pragma unroll
            for (int j = 0; j < 4; j++) lac[i][j] = 0.f;
#pragma unroll
        for (int ks = 0; ks < 16; ks++) {
            uint2 aLo = *(uint2*)(smem + OFF_XS + (((p0 + g)     * XPADF) + ks * 8 + 2 * tg) * 4);
            uint2 aHi = *(uint2*)(smem + OFF_XS + (((p0 + g + 8) * XPADF) + ks * 8 + 2 * tg) * 4);
#pragma unroll
            for (int nb = 0; nb < 8; nb++) {
                uint2 bb = *(uint2*)(smem + OFF_WS + (((nb * 8 + g) * WPADF) + ks * 8 + 2 * tg) * 4);
                mma_tf32(lac[nb], aLo.x, aHi.x, aLo.y, aHi.y, bb.x, bb.y);
            }
        }

        // ---- softmax over k (rows p0+g, p0+g+8), all in regs ----
        {
            float v0[16], v1[16];
            float m0 = -1e30f, m1 = -1e30f;
#pragma unroll
            for (int i = 0; i < 16; i++) {
                int nt = i >> 1, j = i & 1;
                v0[i] = lac[nt][j]     + bias[i];
                v1[i] = lac[nt][2 + j] + bias[i];
                m0 = fmaxf(m0, v0[i]);
                m1 = fmaxf(m1, v1[i]);
            }
            m0 = fmaxf(m0, __shfl_xor_sync(0xffffffffu, m0, 1));
            m0 = fmaxf(m0, __shfl_xor_sync(0xffffffffu, m0, 2));
            m1 = fmaxf(m1, __shfl_xor_sync(0xffffffffu, m1, 1));
            m1 = fmaxf(m1, __shfl_xor_sync(0xffffffffu, m1, 2));
            float s0 = 0.f, s1 = 0.f;
#pragma unroll
            for (int i = 0; i < 16; i++) {
                v0[i] = __expf(v0[i] - m0);  s0 += v0[i];
                v1[i] = __expf(v1[i] - m1);  s1 += v1[i];
            }
            s0 += __shfl_xor_sync(0xffffffffu, s0, 1);
            s0 += __shfl_xor_sync(0xffffffffu, s0, 2);
            s1 += __shfl_xor_sync(0xffffffffu, s1, 1);
            s1 += __shfl_xor_sync(0xffffffffu, s1, 2);
            const float ir0 = 1.0f / s0, ir1 = 1.0f / s1;

#pragma unroll
            for (int i = 0; i < 16; i++) {
                const int k = (i >> 1) * 8 + tg * 2 + (i & 1);
                float a0v = tf32r(v0[i] * ir0);
                float a1v = tf32r(v1[i] * ir1);
                ap[i] += a0v + a1v;   // must match what GEMM2 consumes
                *(float*)(smem + OFF_AS + (k * APADF + p0 + pg) * 4)     = a0v;
                *(float*)(smem + OFF_AS + (k * APADF + p0 + 8 + pg) * 4) = a1v;
            }
        }
        __syncthreads();

        // ---- GEMM2: vlad[16mw..+15][64nh..+63] += a · x̂ ----
#pragma unroll
        for (int ks = 0; ks < 16; ks++) {
            uint2 aLo = *(uint2*)(smem + OFF_AS + (((mw * 16 + g)     * APADF) + ks * 8 + 2 * tg) * 4);
            uint2 aHi = *(uint2*)(smem + OFF_AS + (((mw * 16 + g + 8) * APADF) + ks * 8 + 2 * tg) * 4);
#pragma unroll
            for (int nb = 0; nb < 8; nb++) {
                const int col = nh * 64 + nb * 8 + pg;
                uint32_t b0 = *(uint32_t*)(smem + OFF_XS + (((ks * 8 + tg)     * XPADF) + col) * 4);
                uint32_t b1 = *(uint32_t*)(smem + OFF_XS + (((ks * 8 + tg + 4) * XPADF) + col) * 4);
                mma_tf32(vacc[nb], aLo.x, aHi.x, aLo.y, aHi.y, b0, b1);
            }
        }
    }

    // ---- write vlad partials ----
    {
        float* vp = g_vlad_part + (size_t)(n * NCHUNK + ch) * KK * CC;
        const int k0 = mw * 16 + g;
#pragma unroll
        for (int nt = 0; nt < 8; nt++) {
            const int c = nh * 64 + nt * 8 + tg * 2;
            *(float2*)&vp[k0 * CC + c]       = make_float2(vacc[nt][0], vacc[nt][1]);
            *(float2*)&vp[(k0 + 8) * CC + c] = make_float2(vacc[nt][2], vacc[nt][3]);
        }
    }
    // ---- asum reduce: over g (shfl), then across warps via smem ----
#pragma unroll
    for (int i = 0; i < 16; i++) {
        ap[i] += __shfl_xor_sync(0xffffffffu, ap[i], 4);
        ap[i] += __shfl_xor_sync(0xffffffffu, ap[i], 8);
        ap[i] += __shfl_xor_sync(0xffffffffu, ap[i], 16);
    }
    if (lane < 4) {   // lane == tg, g == 0
#pragma unroll
        for (int i = 0; i < 16; i++)
            asr[wid * 64 + (i >> 1) * 8 + lane * 2 + (i & 1)] = ap[i];
    }
    __syncthreads();
    if (tid < KK) {
        float t = 0.f;
#pragma unroll
        for (int w = 0; w < 8; w++) t += asr[w * 64 + tid];
        g_asum_part[(n * NCHUNK + ch) * KK + tid] = t;
    }
}

// ---------------------------------------------------------------------------
// Kernel 2: reduce chunk partials, centroid subtract, intra-normalize, fc
// ---------------------------------------------------------------------------
__global__ void netvlad_k2(const float* __restrict__ centroids,
                           const float* __restrict__ fc_w)
{
    const int kg = blockIdx.x;      // 0..15
    const int n  = blockIdx.y;      // 0..31
    const int c  = threadIdx.x;     // 0..127
    __shared__ float sred[4];

    float acc = 0.f;
    for (int kk = 0; kk < 4; kk++) {
        const int k = kg * 4 + kk;
        float asum = 0.f;
#pragma unroll
        for (int chn = 0; chn < NCHUNK; chn++)
            asum += g_asum_part[(n * NCHUNK + chn) * KK + k];

        float v = -asum * centroids[k * CC + c];
#pragma unroll
        for (int chn = 0; chn < NCHUNK; chn++)
            v += g_vlad_part[((size_t)(n * NCHUNK + chn) * KK + k) * CC + c];

        float ss = v * v;
#pragma unroll
        for (int off = 16; off > 0; off >>= 1)
            ss += __shfl_xor_sync(0xffffffffu, ss, off);
        if ((c & 31) == 0) sred[c >> 5] = ss;
        __syncthreads();
        float tot = sred[0] + sred[1] + sred[2] + sred[3];
        __syncthreads();

        float inv = 1.0f / fmaxf(sqrtf(tot), 1e-12f);
        acc += v * inv * fc_w[k];
    }
    g_outpart[(n * 16 + kg) * CC + c] = acc;
}

// ---------------------------------------------------------------------------
// Kernel 3: final deterministic reduction over the 16 k-groups
// ---------------------------------------------------------------------------
__global__ void netvlad_k3(float* __restrict__ out)
{
    const int n = blockIdx.x;
    const int c = threadIdx.x;
    float s = 0.f;
#pragma unroll
    for (int kg = 0; kg < 16; kg++)
        s += g_outpart[(n * 16 + kg) * CC + c];
    out[n * CC + c] = s;
}

// ---------------------------------------------------------------------------
extern "C" void kernel_launch(void* const* d_in, const int* in_sizes, int n_in,
                              void* d_out, int out_size)
{
    const float* x      = (const float*)d_in[0];  // [32,128,64,64]
    const float* conv_w = (const float*)d_in[1];  // [64,128]
    const float* conv_b = (const float*)d_in[2];  // [64]
    const float* cent   = (const float*)d_in[3];  // [64,128]
    const float* fc_w   = (const float*)d_in[4];  // [1,64]
    float* out = (float*)d_out;                   // [32,128]

    cudaFuncSetAttribute(netvlad_k1,
                         cudaFuncAttributeMaxDynamicSharedMemorySize,
                         SMEM_BYTES);

    dim3 g1(NCHUNK, NN);
    netvlad_k1<<<g1, THREADS, SMEM_BYTES>>>(x, conv_w, conv_b);

    dim3 g2(16, NN);
    netvlad_k2<<<g2, CC>>>(cent, fc_w);

    netvlad_k3<<<NN, CC>>>(out);
}